// round 7
// baseline (speedup 1.0000x reference)
#include <cuda_runtime.h>

#define E_EDGES 250000
#define TILE_E  128
#define NBLOCKS ((E_EDGES + TILE_E - 1) / TILE_E)

using u64 = unsigned long long;

__device__ float g_wsh[12288];   // pre-swizzled W image (exact smem layout)

__device__ __forceinline__ u64 ffma2(u64 a, u64 b, u64 c) {
    u64 d;
    asm("fma.rn.f32x2 %0, %1, %2, %3;" : "=l"(d) : "l"(a), "l"(b), "l"(c));
    return d;
}
__device__ __forceinline__ u64 dup2(float x) {
    u64 d;
    asm("mov.b64 %0, {%1, %1};" : "=l"(d) : "f"(x));
    return d;
}
__device__ __forceinline__ float lo32(u64 v) { return __uint_as_float((unsigned)(v & 0xffffffffu)); }
__device__ __forceinline__ float hi32(u64 v) { return __uint_as_float((unsigned)(v >> 32)); }

// g_wsh word ((d*3+r)*32 + pg)*2 + b = W[d][ (2*pg+b)*3 + r ]
__global__ void prep_w_kernel(const float* __restrict__ W) {
    int o = blockIdx.x * 256 + threadIdx.x;
    if (o < 12288) {
        int b  = o & 1;
        int pg = (o >> 1) & 31;
        int dr = o >> 6;
        int d  = dr / 3, r = dr - 3 * d;
        g_wsh[o] = W[d * 192 + (2 * pg + b) * 3 + r];
    }
}

// Shared layout (bytes):
//   wsh  : float2[64*3*32] [0, 49152)
//   invs : float [64*132]  [49152, 82944)   d-major rows, stride 132 (float4-aligned)
//   shs  : float [128*12]  [82944, 89088)
//   stage: overlay [0, 37376)  per-warp 2 rows x 292 words
#define SMEM_BYTES 89088

__global__ __launch_bounds__(512, 2)
void sh_tensor_embed_kernel(const float* __restrict__ vec,
                            const float* __restrict__ inv,
                            float* __restrict__ out) {
    extern __shared__ char sm[];
    float* smf  = (float*)sm;
    float* invs = (float*)(sm + 49152);
    float* shs  = (float*)(sm + 82944);

    const int tid = threadIdx.x;
    const int e0  = blockIdx.x * TILE_E;

    // ---- W fill: linear conflict-free copy of pre-swizzled image ----
    #pragma unroll
    for (int it = 0; it < 6; it++) {
        int idx = it * 512 + tid;
        ((float4*)smf)[idx] = ((const float4*)g_wsh)[idx];
    }
    // ---- edge-invariant tile (transposed, stride 132) ----
    for (int idx = tid; idx < TILE_E * 64; idx += 512) {
        int el = idx >> 6, d = idx & 63;
        int e = e0 + el; if (e >= E_EDGES) e = E_EDGES - 1;
        invs[d * 132 + el] = inv[(size_t)e * 64 + d];
    }
    // ---- spherical harmonics per edge (rows padded to 12) ----
    if (tid < TILE_E) {
        int e = e0 + tid; if (e >= E_EDGES) e = E_EDGES - 1;
        float x = vec[(size_t)e * 3 + 0];
        float y = vec[(size_t)e * 3 + 1];
        float z = vec[(size_t)e * 3 + 2];
        float r = rsqrtf(x * x + y * y + z * z);
        x *= r; y *= r; z *= r;
        const float s3  = 1.7320508075688772f;
        const float s5  = 2.2360679774997896f;
        const float s15 = 3.8729833462074170f;
        float* o = shs + tid * 12;
        o[0] = 1.0f;
        o[1] = s3 * x;
        o[2] = s3 * y;
        o[3] = s3 * z;
        o[4] = s15 * x * z;
        o[5] = s15 * x * y;
        o[6] = s5 * (y * y - 0.5f * (x * x + z * z));
        o[7] = s15 * y * z;
        o[8] = 0.5f * s15 * (z * z - x * x);
    }
    __syncthreads();

    // warp tile: 32 channels (half h) x 16 edges (octet-pair g); lane = eh*16 + cp
    const int lane = tid & 31;
    const int wid  = tid >> 5;           // 0..15
    const int cp   = lane & 15;
    const int eh   = lane >> 4;
    const int h    = wid & 1;            // channels [32h, 32h+32)
    const int g    = wid >> 1;           // edges [16g, 16g+16)  (g = 0..7)

    u64 acc[8][3];
    #pragma unroll
    for (int j = 0; j < 8; j++)
        #pragma unroll
        for (int r = 0; r < 3; r++)
            acc[j][r] = 0ull;

    const float2* wp = (const float2*)smf + (h * 16 + cp);
    const float*  ip = invs + g * 16 + eh * 8;

    #pragma unroll 2
    for (int d = 0; d < 64; d++) {
        u64 wv[3];
        #pragma unroll
        for (int r = 0; r < 3; r++)
            wv[r] = *(const u64*)(wp + (d * 3 + r) * 32);       // 1 phase each
        {
            float4 iva = *(const float4*)(ip + d * 132);        // broadcast
            #pragma unroll
            for (int j = 0; j < 4; j++) {
                u64 pv = dup2(j == 0 ? iva.x : j == 1 ? iva.y : j == 2 ? iva.z : iva.w);
                #pragma unroll
                for (int r = 0; r < 3; r++)
                    acc[j][r] = ffma2(pv, wv[r], acc[j][r]);
            }
        }
        {
            float4 ivb = *(const float4*)(ip + d * 132 + 4);    // broadcast
            #pragma unroll
            for (int j = 0; j < 4; j++) {
                u64 pv = dup2(j == 0 ? ivb.x : j == 1 ? ivb.y : j == 2 ? ivb.z : ivb.w);
                #pragma unroll
                for (int r = 0; r < 3; r++)
                    acc[4 + j][r] = ffma2(pv, wv[r], acc[4 + j][r]);
            }
        }
    }

    // ---- epilogue: warp-private staging; warp slice per edge = contiguous 288 floats ----
    __syncthreads();                       // wsh/invs reads done before overlay write
    float* stage = smf + wid * 584;        // 2 rows x 292 words, warp-private

    #pragma unroll
    for (int s = 0; s < 8; s++) {
        {
            int el = g * 16 + eh * 8 + s;
            const float* sb = shs + el * 12;
            float4 sa  = *(const float4*)sb;
            float4 sbv = *(const float4*)(sb + 4);
            float  s8  = sb[8];
            float sv[9] = {sa.x, sa.y, sa.z, sa.w, sbv.x, sbv.y, sbv.z, sbv.w, s8};
            float wa[3], wb[3];
            #pragma unroll
            for (int r = 0; r < 3; r++) { wa[r] = lo32(acc[s][r]); wb[r] = hi32(acc[s][r]); }
            float* rowp = stage + eh * 292 + cp * 18;
            #pragma unroll
            for (int k = 0; k < 9; k += 2) {
                float v0 = sv[k] * ((k == 0) ? wa[0] : (k < 4) ? wa[1] : wa[2]);
                float v1 = (k + 1 < 9) ? sv[k + 1] * ((k + 1 < 4) ? wa[1] : wa[2]) : 0.f;
                if (k + 1 < 9) *(float2*)(rowp + k) = make_float2(v0, v1);
            }
            // k=8 pairs with channel-b k=0
            *(float2*)(rowp + 8) = make_float2(sv[8] * wa[2], sv[0] * wb[0]);
            #pragma unroll
            for (int k = 1; k < 9; k += 2) {
                float v0 = sv[k] * ((k < 4) ? wb[1] : wb[2]);
                float v1 = sv[k + 1] * ((k + 1 < 4) ? wb[1] : wb[2]);
                *(float2*)(rowp + 9 + k) = make_float2(v0, v1);
            }
        }
        __syncwarp();
        #pragma unroll
        for (int t = 0; t < 2; t++) {
            int e = e0 + g * 16 + t * 8 + s;
            if (e < E_EDGES) {
                const float4* src = (const float4*)(stage + t * 292);
                float4* dst = (float4*)(out + (size_t)e * 576 + h * 288);
                dst[lane]      = src[lane];
                dst[lane + 32] = src[lane + 32];
                if (lane < 8) dst[lane + 64] = src[lane + 64];
            }
        }
        __syncwarp();
    }
}

extern "C" void kernel_launch(void* const* d_in, const int* in_sizes, int n_in,
                              void* d_out, int out_size) {
    const float* vec = nullptr;
    const float* inv = nullptr;
    const float* W   = nullptr;
    for (int i = 0; i < n_in; i++) {
        if      (in_sizes[i] == E_EDGES * 3)  vec = (const float*)d_in[i];
        else if (in_sizes[i] == E_EDGES * 64) inv = (const float*)d_in[i];
        else if (in_sizes[i] == 64 * 192)     W   = (const float*)d_in[i];
    }
    prep_w_kernel<<<48, 256>>>(W);
    cudaFuncSetAttribute(sh_tensor_embed_kernel,
                         cudaFuncAttributeMaxDynamicSharedMemorySize, SMEM_BYTES);
    sh_tensor_embed_kernel<<<NBLOCKS, 512, SMEM_BYTES>>>(vec, inv, (float*)d_out);
}

// round 8
// speedup vs baseline: 1.3449x; 1.3449x over previous
#include <cuda_runtime.h>

#define E_EDGES 250000
#define TILE_E  64
#define NBLOCKS ((E_EDGES + TILE_E - 1) / TILE_E)
#define GRID    444   /* 3 CTAs x 148 SMs, persistent */

using u64 = unsigned long long;

__device__ float g_wsh[12288];   // pre-swizzled W image (exact smem layout)

__device__ __forceinline__ u64 ffma2(u64 a, u64 b, u64 c) {
    u64 d;
    asm("fma.rn.f32x2 %0, %1, %2, %3;" : "=l"(d) : "l"(a), "l"(b), "l"(c));
    return d;
}
__device__ __forceinline__ u64 dup2(float x) {
    u64 d;
    asm("mov.b64 %0, {%1, %1};" : "=l"(d) : "f"(x));
    return d;
}
__device__ __forceinline__ float lo32(u64 v) { return __uint_as_float((unsigned)(v & 0xffffffffu)); }
__device__ __forceinline__ float hi32(u64 v) { return __uint_as_float((unsigned)(v >> 32)); }

// g_wsh word ((d*3+r)*32 + pg)*2 + b = W[d][ (2*pg+b)*3 + r ]
__global__ void prep_w_kernel(const float* __restrict__ W) {
    int o = blockIdx.x * 256 + threadIdx.x;
    if (o < 12288) {
        int b  = o & 1;
        int pg = (o >> 1) & 31;
        int dr = o >> 6;
        int d  = dr / 3, r = dr - 3 * d;
        g_wsh[o] = W[d * 192 + (2 * pg + b) * 3 + r];
    }
}

// Shared layout (bytes):
//   wsh  : float[12288]  [0, 49152)        persistent across tiles
//   invs : [49152, 67840)  rows stride 68 (17408B used); region padded to 18688B
//          because the epilogue stage (8 warps x 584 floats) overlays it
//   shs  : float[64*12]  [67840, 70912)
#define SMEM_BYTES 70912

__device__ __forceinline__ void sh_from_vec(float x, float y, float z, float* o) {
    float r = rsqrtf(x * x + y * y + z * z);
    x *= r; y *= r; z *= r;
    const float s3  = 1.7320508075688772f;
    const float s5  = 2.2360679774997896f;
    const float s15 = 3.8729833462074170f;
    o[0] = 1.0f;
    o[1] = s3 * x;
    o[2] = s3 * y;
    o[3] = s3 * z;
    o[4] = s15 * x * z;
    o[5] = s15 * x * y;
    o[6] = s5 * (y * y - 0.5f * (x * x + z * z));
    o[7] = s15 * y * z;
    o[8] = 0.5f * s15 * (z * z - x * x);
}

__global__ __launch_bounds__(256, 3)
void sh_tensor_embed_kernel(const float* __restrict__ vec,
                            const float* __restrict__ inv,
                            float* __restrict__ out) {
    extern __shared__ char sm[];
    float* smf  = (float*)sm;
    float* invs = (float*)(sm + 49152);
    float* shs  = (float*)(sm + 67840);

    const int tid  = threadIdx.x;
    const int lane = tid & 31;
    const int wid  = tid >> 5;
    const int cp   = lane & 15;
    const int eh   = lane >> 4;
    const int h    = wid & 1;            // channels [32h, 32h+32)
    const int g    = wid >> 1;           // edges [16g, 16g+16)

    // ---- one-time W fill (persists across tiles) ----
    #pragma unroll
    for (int it = 0; it < 12; it++) {
        int idx = it * 256 + tid;
        ((float4*)smf)[idx] = ((const float4*)g_wsh)[idx];
    }
    // ---- fill first tile's invs + shs ----
    {
        int e0 = blockIdx.x * TILE_E;
        #pragma unroll
        for (int k = 0; k < 16; k++) {
            int idx = tid + 256 * k;
            int el = idx >> 6, d = idx & 63;
            int e = e0 + el; if (e >= E_EDGES) e = E_EDGES - 1;
            invs[d * 68 + el] = inv[(size_t)e * 64 + d];
        }
        if (tid < TILE_E) {
            int e = e0 + tid; if (e >= E_EDGES) e = E_EDGES - 1;
            sh_from_vec(vec[(size_t)e * 3], vec[(size_t)e * 3 + 1], vec[(size_t)e * 3 + 2],
                        shs + tid * 12);
        }
    }
    __syncthreads();

    const float2* wp = (const float2*)smf + (h * 16 + cp);
    float* stage = invs + wid * 584;     // overlay (invs dead during epilogue)

    for (int tile = blockIdx.x; tile < NBLOCKS; tile += GRID) {
        const int e0 = tile * TILE_E;

        // ---- mainloop: channels {2*(h*16+cp)}, 16 edges (2 octets via eh) ----
        u64 acc[8][3];
        #pragma unroll
        for (int j = 0; j < 8; j++)
            #pragma unroll
            for (int r = 0; r < 3; r++)
                acc[j][r] = 0ull;

        const float* ip = invs + g * 16 + eh * 8;

        #pragma unroll 2
        for (int d = 0; d < 64; d++) {
            u64 wv[3];
            #pragma unroll
            for (int r = 0; r < 3; r++)
                wv[r] = *(const u64*)(wp + (d * 3 + r) * 32);   // 1 phase each
            float iv[8];
            *(float4*)&iv[0] = *(const float4*)(ip + d * 68);   // 2-addr broadcast
            *(float4*)&iv[4] = *(const float4*)(ip + d * 68 + 4);
            #pragma unroll
            for (int j = 0; j < 8; j++) {
                u64 pv = dup2(iv[j]);
                #pragma unroll
                for (int r = 0; r < 3; r++)
                    acc[j][r] = ffma2(pv, wv[r], acc[j][r]);
            }
        }
        __syncthreads();                 // invs reads done -> stage overlay safe

        // ---- prefetch next tile while epilogue runs (LDG hidden) ----
        const int nt = tile + GRID;
        const bool nxt = nt < NBLOCKS;
        float pv[16];
        float vx = 0.f, vy = 0.f, vz = 0.f;
        if (nxt) {
            int ne0 = nt * TILE_E;
            #pragma unroll
            for (int k = 0; k < 16; k++) {
                int idx = tid + 256 * k;
                int el = idx >> 6, d = idx & 63;
                int e = ne0 + el; if (e >= E_EDGES) e = E_EDGES - 1;
                pv[k] = inv[(size_t)e * 64 + d];
            }
            if (tid < TILE_E) {
                int e = ne0 + tid; if (e >= E_EDGES) e = E_EDGES - 1;
                vx = vec[(size_t)e * 3];
                vy = vec[(size_t)e * 3 + 1];
                vz = vec[(size_t)e * 3 + 2];
            }
        }

        // ---- epilogue: warp-private staging, coalesced copy-out ----
        #pragma unroll
        for (int s = 0; s < 8; s++) {
            {
                int el = g * 16 + eh * 8 + s;
                const float* sb = shs + el * 12;
                float4 sa  = *(const float4*)sb;
                float4 sbv = *(const float4*)(sb + 4);
                float  s8  = sb[8];
                float sv[9] = {sa.x, sa.y, sa.z, sa.w, sbv.x, sbv.y, sbv.z, sbv.w, s8};
                float wa[3], wb[3];
                #pragma unroll
                for (int r = 0; r < 3; r++) { wa[r] = lo32(acc[s][r]); wb[r] = hi32(acc[s][r]); }
                float v[18];
                #pragma unroll
                for (int k = 0; k < 9; k++) {
                    int r = (k == 0) ? 0 : ((k < 4) ? 1 : 2);
                    v[k]     = sv[k] * wa[r];
                    v[9 + k] = sv[k] * wb[r];
                }
                float* rowp = stage + eh * 292 + cp * 18;
                #pragma unroll
                for (int p = 0; p < 9; p++)
                    *(float2*)(rowp + 2 * p) = make_float2(v[2 * p], v[2 * p + 1]);
            }
            __syncwarp();
            #pragma unroll
            for (int t = 0; t < 2; t++) {
                int e = e0 + g * 16 + t * 8 + s;
                if (e < E_EDGES) {
                    const float4* src = (const float4*)(stage + t * 292);
                    float4* dst = (float4*)(out + (size_t)e * 576 + h * 288);
                    dst[lane]      = src[lane];
                    dst[lane + 32] = src[lane + 32];
                    if (lane < 8) dst[lane + 64] = src[lane + 64];
                }
            }
            __syncwarp();
        }
        __syncthreads();                 // stage reads done -> invs refill safe

        // ---- commit prefetched tile ----
        if (nxt) {
            #pragma unroll
            for (int k = 0; k < 16; k++) {
                int idx = tid + 256 * k;
                int el = idx >> 6, d = idx & 63;
                invs[d * 68 + el] = pv[k];
            }
            if (tid < TILE_E)
                sh_from_vec(vx, vy, vz, shs + tid * 12);
        }
        __syncthreads();
    }
}

extern "C" void kernel_launch(void* const* d_in, const int* in_sizes, int n_in,
                              void* d_out, int out_size) {
    const float* vec = nullptr;
    const float* inv = nullptr;
    const float* W   = nullptr;
    for (int i = 0; i < n_in; i++) {
        if      (in_sizes[i] == E_EDGES * 3)  vec = (const float*)d_in[i];
        else if (in_sizes[i] == E_EDGES * 64) inv = (const float*)d_in[i];
        else if (in_sizes[i] == 64 * 192)     W   = (const float*)d_in[i];
    }
    prep_w_kernel<<<48, 256>>>(W);
    cudaFuncSetAttribute(sh_tensor_embed_kernel,
                         cudaFuncAttributeMaxDynamicSharedMemorySize, SMEM_BYTES);
    sh_tensor_embed_kernel<<<GRID, 256, SMEM_BYTES>>>(vec, inv, (float*)d_out);
}

// round 9
// speedup vs baseline: 1.4396x; 1.0705x over previous
#include <cuda_runtime.h>

#define E_EDGES 250000
#define TILE_E  64
#define NBLOCKS ((E_EDGES + TILE_E - 1) / TILE_E)
#define GRID    444   /* 3 CTAs x 148 SMs, persistent */

using u64 = unsigned long long;

__device__ float g_wsh[12288];   // pre-swizzled W image (exact smem layout)

__device__ __forceinline__ u64 ffma2(u64 a, u64 b, u64 c) {
    u64 d;
    asm("fma.rn.f32x2 %0, %1, %2, %3;" : "=l"(d) : "l"(a), "l"(b), "l"(c));
    return d;
}
__device__ __forceinline__ u64 dup2(float x) {
    u64 d;
    asm("mov.b64 %0, {%1, %1};" : "=l"(d) : "f"(x));
    return d;
}
__device__ __forceinline__ float lo32(u64 v) { return __uint_as_float((unsigned)(v & 0xffffffffu)); }
__device__ __forceinline__ float hi32(u64 v) { return __uint_as_float((unsigned)(v >> 32)); }

// W layout per (d,h): base = d*192 + h*96 floats
//   blockA [0,64):  cp*4 -> {W[c0][r0], W[c1][r0], W[c0][r1], W[c1][r1]}   (c0=h*32+2cp)
//   blockB [64,96): cp*2 -> {W[c0][r2], W[c1][r2]}
__global__ void prep_w_kernel(const float* __restrict__ W) {
    int o = blockIdx.x * 256 + threadIdx.x;
    if (o < 12288) {
        int d    = o / 192;
        int rem  = o - d * 192;
        int h    = rem / 96;
        int rem2 = rem - h * 96;
        int c, r;
        if (rem2 < 64) {
            int cp = rem2 >> 2, q = rem2 & 3;
            c = h * 32 + 2 * cp + (q & 1);
            r = q >> 1;
        } else {
            int rem3 = rem2 - 64;
            int cp = rem3 >> 1;
            c = h * 32 + 2 * cp + (rem3 & 1);
            r = 2;
        }
        g_wsh[o] = W[d * 192 + c * 3 + r];
    }
}

// Shared layout (bytes):
//   wsh  : float[12288]  [0, 49152)        persistent across tiles
//   invs : [49152, 67840)  rows stride 68 (17408B used); padded to 18688B
//          for the epilogue stage overlay (8 warps x 584 floats)
//   shs  : float[64*12]  [67840, 70912)
#define SMEM_BYTES 70912

// fill index remap: warp covers 4 edges x 8 consecutive d -> conflict-free STS
__device__ __forceinline__ void fill_map(int idx, int& el, int& d) {
    el = (idx & 3) | ((idx >> 3) & 0x3C);
    d  = ((idx >> 2) & 7) | ((idx >> 6) & 0x38);
}

__device__ __forceinline__ void sh_from_vec(float x, float y, float z, float* o) {
    float r = rsqrtf(x * x + y * y + z * z);
    x *= r; y *= r; z *= r;
    const float s3  = 1.7320508075688772f;
    const float s5  = 2.2360679774997896f;
    const float s15 = 3.8729833462074170f;
    o[0] = 1.0f;
    o[1] = s3 * x;
    o[2] = s3 * y;
    o[3] = s3 * z;
    o[4] = s15 * x * z;
    o[5] = s15 * x * y;
    o[6] = s5 * (y * y - 0.5f * (x * x + z * z));
    o[7] = s15 * y * z;
    o[8] = 0.5f * s15 * (z * z - x * x);
}

__global__ __launch_bounds__(256, 3)
void sh_tensor_embed_kernel(const float* __restrict__ vec,
                            const float* __restrict__ inv,
                            float* __restrict__ out) {
    extern __shared__ char sm[];
    float* smf  = (float*)sm;
    float* invs = (float*)(sm + 49152);
    float* shs  = (float*)(sm + 67840);

    const int tid  = threadIdx.x;
    const int lane = tid & 31;
    const int wid  = tid >> 5;
    const int cp   = lane & 15;
    const int eh   = lane >> 4;
    const int h    = wid & 1;            // channels [32h, 32h+32)
    const int g    = wid >> 1;           // edges [16g, 16g+16)

    // ---- one-time W fill (persists across tiles) ----
    #pragma unroll
    for (int it = 0; it < 12; it++) {
        int idx = it * 256 + tid;
        ((float4*)smf)[idx] = ((const float4*)g_wsh)[idx];
    }
    // ---- fill first tile's invs + shs ----
    {
        int e0 = blockIdx.x * TILE_E;
        #pragma unroll
        for (int k = 0; k < 16; k++) {
            int el, d;
            fill_map(tid + 256 * k, el, d);
            int e = e0 + el; if (e >= E_EDGES) e = E_EDGES - 1;
            invs[d * 68 + el] = inv[(size_t)e * 64 + d];   // conflict-free STS
        }
        if (tid < TILE_E) {
            int e = e0 + tid; if (e >= E_EDGES) e = E_EDGES - 1;
            sh_from_vec(vec[(size_t)e * 3], vec[(size_t)e * 3 + 1], vec[(size_t)e * 3 + 2],
                        shs + tid * 12);
        }
    }
    __syncthreads();

    const char* wbaseA = (const char*)(smf + h * 96 + cp * 4);
    const char* wbaseB = (const char*)(smf + h * 96 + 64 + cp * 2);
    float* stage = invs + wid * 584;     // overlay (invs dead during epilogue)

    for (int tile = blockIdx.x; tile < NBLOCKS; tile += GRID) {
        const int e0 = tile * TILE_E;

        // ---- mainloop ----
        u64 acc[8][3];
        #pragma unroll
        for (int j = 0; j < 8; j++)
            #pragma unroll
            for (int r = 0; r < 3; r++)
                acc[j][r] = 0ull;

        const float* ip = invs + g * 16 + eh * 8;

        #pragma unroll 2
        for (int d = 0; d < 64; d++) {
            ulonglong2 wab = *(const ulonglong2*)(wbaseA + d * 768);  // {wv0, wv1}
            u64 wv2        = *(const u64*)      (wbaseB + d * 768);
            float iv[8];
            *(float4*)&iv[0] = *(const float4*)(ip + d * 68);   // broadcast LDS.128
            *(float4*)&iv[4] = *(const float4*)(ip + d * 68 + 4);
            #pragma unroll
            for (int j = 0; j < 8; j++) {
                u64 pv = dup2(iv[j]);
                acc[j][0] = ffma2(pv, wab.x, acc[j][0]);
                acc[j][1] = ffma2(pv, wab.y, acc[j][1]);
                acc[j][2] = ffma2(pv, wv2,   acc[j][2]);
            }
        }
        __syncthreads();                 // invs reads done -> stage overlay safe

        // ---- prefetch next tile while epilogue runs ----
        const int nt = tile + GRID;
        const bool nxt = nt < NBLOCKS;
        float pv[16];
        float vx = 0.f, vy = 0.f, vz = 0.f;
        if (nxt) {
            int ne0 = nt * TILE_E;
            #pragma unroll
            for (int k = 0; k < 16; k++) {
                int el, d;
                fill_map(tid + 256 * k, el, d);
                int e = ne0 + el; if (e >= E_EDGES) e = E_EDGES - 1;
                pv[k] = inv[(size_t)e * 64 + d];
            }
            if (tid < TILE_E) {
                int e = ne0 + tid; if (e >= E_EDGES) e = E_EDGES - 1;
                vx = vec[(size_t)e * 3];
                vy = vec[(size_t)e * 3 + 1];
                vz = vec[(size_t)e * 3 + 2];
            }
        }

        // ---- epilogue: warp-private staging, coalesced copy-out ----
        #pragma unroll
        for (int s = 0; s < 8; s++) {
            {
                int el = g * 16 + eh * 8 + s;
                const float* sb = shs + el * 12;
                float4 sa  = *(const float4*)sb;
                float4 sbv = *(const float4*)(sb + 4);
                float  s8  = sb[8];
                float sv[9] = {sa.x, sa.y, sa.z, sa.w, sbv.x, sbv.y, sbv.z, sbv.w, s8};
                float wa[3], wb[3];
                #pragma unroll
                for (int r = 0; r < 3; r++) { wa[r] = lo32(acc[s][r]); wb[r] = hi32(acc[s][r]); }
                float v[18];
                #pragma unroll
                for (int k = 0; k < 9; k++) {
                    int r = (k == 0) ? 0 : ((k < 4) ? 1 : 2);
                    v[k]     = sv[k] * wa[r];
                    v[9 + k] = sv[k] * wb[r];
                }
                float* rowp = stage + eh * 292 + cp * 18;
                #pragma unroll
                for (int p = 0; p < 9; p++)
                    *(float2*)(rowp + 2 * p) = make_float2(v[2 * p], v[2 * p + 1]);
            }
            __syncwarp();
            #pragma unroll
            for (int t = 0; t < 2; t++) {
                int e = e0 + g * 16 + t * 8 + s;
                if (e < E_EDGES) {
                    const float4* src = (const float4*)(stage + t * 292);
                    float4* dst = (float4*)(out + (size_t)e * 576 + h * 288);
                    dst[lane]      = src[lane];
                    dst[lane + 32] = src[lane + 32];
                    if (lane < 8) dst[lane + 64] = src[lane + 64];
                }
            }
            __syncwarp();
        }
        __syncthreads();                 // stage reads done -> invs refill safe

        // ---- commit prefetched tile (conflict-free STS) ----
        if (nxt) {
            #pragma unroll
            for (int k = 0; k < 16; k++) {
                int el, d;
                fill_map(tid + 256 * k, el, d);
                invs[d * 68 + el] = pv[k];
            }
            if (tid < TILE_E)
                sh_from_vec(vx, vy, vz, shs + tid * 12);
        }
        __syncthreads();
    }
}

extern "C" void kernel_launch(void* const* d_in, const int* in_sizes, int n_in,
                              void* d_out, int out_size) {
    const float* vec = nullptr;
    const float* inv = nullptr;
    const float* W   = nullptr;
    for (int i = 0; i < n_in; i++) {
        if      (in_sizes[i] == E_EDGES * 3)  vec = (const float*)d_in[i];
        else if (in_sizes[i] == E_EDGES * 64) inv = (const float*)d_in[i];
        else if (in_sizes[i] == 64 * 192)     W   = (const float*)d_in[i];
    }
    prep_w_kernel<<<48, 256>>>(W);
    cudaFuncSetAttribute(sh_tensor_embed_kernel,
                         cudaFuncAttributeMaxDynamicSharedMemorySize, SMEM_BYTES);
    sh_tensor_embed_kernel<<<GRID, 256, SMEM_BYTES>>>(vec, inv, (float*)d_out);
}